// round 1
// baseline (speedup 1.0000x reference)
#include <cuda_runtime.h>

#define GAMMA 0.001f
#define NIMG 4096
#define MSUP 8192
#define KDIM 784
#define NCLS 4

#define BN 64
#define BM 128
#define KC 16

// scratch (no allocs allowed)
__device__ float g_feats[NIMG * KDIM];
__device__ float g_s2[MSUP];
__device__ float g_f2[NIMG];
__device__ float g_scratch[2 * NIMG * NCLS];

// ---------------------------------------------------------------------------
// Conv pipeline: per-image block. Padded smem buffers remove bounds checks.
// feats layout matches NCHW flatten: idx = c*49 + py*7 + px
// ---------------------------------------------------------------------------
__global__ void __launch_bounds__(128) conv_kernel(
    const float* __restrict__ x,
    const float* __restrict__ w1, const float* __restrict__ b1,
    const float* __restrict__ w2, const float* __restrict__ b2)
{
    __shared__ float sx[30 * 30];        // 28x28 padded by 1
    __shared__ float sp1[8 * 16 * 16];   // 14x14 padded by 1 (in 16x16)
    __shared__ float sw1[72], sb1[8], sw2[1152], sb2[16];

    const int tid = threadIdx.x;
    const int n = blockIdx.x;

    for (int i = tid; i < 900; i += 128) sx[i] = 0.f;
    for (int i = tid; i < 2048; i += 128) sp1[i] = 0.f;
    for (int i = tid; i < 72; i += 128) sw1[i] = w1[i];
    if (tid < 8) sb1[tid] = b1[tid];
    for (int i = tid; i < 1152; i += 128) sw2[i] = w2[i];
    if (tid < 16) sb2[tid] = b2[tid];
    __syncthreads();

    const float* xn = x + (size_t)n * 784;
    for (int i = tid; i < 784; i += 128) {
        int yy = i / 28, xx = i % 28;
        sx[(yy + 1) * 30 + xx + 1] = xn[i];
    }
    __syncthreads();

    // conv1 (SAME) + relu + 2x2 maxpool -> sp1[8][14][14] (padded 16x16)
    for (int o = tid; o < 8 * 14 * 14; o += 128) {
        int c = o / 196, rem = o % 196;
        int py = rem / 14, px = rem % 14;
        float m = 0.f;  // relu output >= 0, so 0 init == -inf init after relu
        #pragma unroll
        for (int sy = 0; sy < 2; sy++) {
            #pragma unroll
            for (int sxx = 0; sxx < 2; sxx++) {
                int y = py * 2 + sy, xx2 = px * 2 + sxx;
                float acc = sb1[c];
                #pragma unroll
                for (int dy = 0; dy < 3; dy++)
                    #pragma unroll
                    for (int dx = 0; dx < 3; dx++)
                        acc += sw1[c * 9 + dy * 3 + dx] * sx[(y + dy) * 30 + xx2 + dx];
                m = fmaxf(m, fmaxf(acc, 0.f));
            }
        }
        sp1[c * 256 + (py + 1) * 16 + px + 1] = m;
    }
    __syncthreads();

    // conv2 (SAME, 8->16) + relu + 2x2 maxpool -> feats[16*7*7]
    for (int o = tid; o < 16 * 7 * 7; o += 128) {
        int c = o / 49, rem = o % 49;
        int py = rem / 7, px = rem % 7;
        float m = 0.f;
        #pragma unroll
        for (int sy = 0; sy < 2; sy++) {
            #pragma unroll
            for (int sxx = 0; sxx < 2; sxx++) {
                int y = py * 2 + sy, xx2 = px * 2 + sxx;
                float acc = sb2[c];
                #pragma unroll
                for (int ic = 0; ic < 8; ic++) {
                    #pragma unroll
                    for (int dy = 0; dy < 3; dy++)
                        #pragma unroll
                        for (int dx = 0; dx < 3; dx++)
                            acc += sw2[c * 72 + ic * 9 + dy * 3 + dx] *
                                   sp1[ic * 256 + (y + dy) * 16 + xx2 + dx];
                }
                m = fmaxf(m, fmaxf(acc, 0.f));
            }
        }
        g_feats[(size_t)n * KDIM + o] = m;
    }
}

// ---------------------------------------------------------------------------
// Row sums of squares: support -> g_s2, feats -> g_f2. One warp per row.
// ---------------------------------------------------------------------------
__global__ void __launch_bounds__(256) sumsq_kernel(const float* __restrict__ support)
{
    int warp = (blockIdx.x * blockDim.x + threadIdx.x) >> 5;
    int lane = threadIdx.x & 31;
    if (warp >= MSUP + NIMG) return;
    const float* row = (warp < MSUP) ? (support + (size_t)warp * KDIM)
                                     : (g_feats + (size_t)(warp - MSUP) * KDIM);
    float s = 0.f;
    for (int k = lane; k < KDIM; k += 32) { float v = row[k]; s += v * v; }
    #pragma unroll
    for (int off = 16; off; off >>= 1) s += __shfl_xor_sync(0xffffffffu, s, off);
    if (lane == 0) {
        if (warp < MSUP) g_s2[warp] = s;
        else             g_f2[warp - MSUP] = s;
    }
}

// ---------------------------------------------------------------------------
// Fused: D = feats @ support^T ; K = exp(-g*(f2+s2-2D)) ; pout += K @ alpha
// Block tile 64(i) x 128(j), thread tile 4x8, KC=16 smem chunks (k-major).
// grid = (NIMG/BN, 2 M-splits); partials into g_scratch (no atomics).
// ---------------------------------------------------------------------------
__global__ void __launch_bounds__(256) gemm_kernel(
    const float* __restrict__ support,
    const float* __restrict__ alpha)
{
    __shared__ float As[KC][BN + 4];    // k-major, 272B rows (16B aligned)
    __shared__ float Bs[KC][BM + 8];    // k-major, 544B rows (16B aligned)
    __shared__ float4 alpha_s[BM];
    __shared__ float s2s[BM];
    __shared__ float f2s[BN];

    const int tid = threadIdx.x;
    const int tx = tid & 15;   // j-group
    const int ty = tid >> 4;   // i-group
    const int ibase = blockIdx.x * BN;
    const int msplit = blockIdx.y;

    if (tid < BN) f2s[tid] = g_f2[ibase + tid];

    float pout[4][4];
    #pragma unroll
    for (int r = 0; r < 4; r++)
        #pragma unroll
        for (int c = 0; c < 4; c++) pout[r][c] = 0.f;

    for (int mt = 0; mt < (MSUP / BM) / 2; mt++) {
        const int jbase = (msplit * ((MSUP / BM) / 2) + mt) * BM;

        if (tid < BM) {
            s2s[tid] = g_s2[jbase + tid];
            alpha_s[tid] = ((const float4*)alpha)[jbase + tid];
        }

        float acc[4][8];
        #pragma unroll
        for (int r = 0; r < 4; r++)
            #pragma unroll
            for (int u = 0; u < 8; u++) acc[r][u] = 0.f;

        for (int kc = 0; kc < KDIM; kc += KC) {
            __syncthreads();
            // A: 64x16 -> As[kk][r]
            #pragma unroll
            for (int it = 0; it < 4; it++) {
                int idx = tid + it * 256;
                int r = idx >> 4, kk = idx & 15;
                As[kk][r] = g_feats[(size_t)(ibase + r) * KDIM + kc + kk];
            }
            // B: 128x16 -> Bs[kk][r]
            #pragma unroll
            for (int it = 0; it < 8; it++) {
                int idx = tid + it * 256;
                int r = idx >> 4, kk = idx & 15;
                Bs[kk][r] = support[(size_t)(jbase + r) * KDIM + kc + kk];
            }
            __syncthreads();

            #pragma unroll
            for (int kk = 0; kk < KC; kk++) {
                float4 av  = *(const float4*)&As[kk][ty * 4];
                float4 bv0 = *(const float4*)&Bs[kk][tx * 8];
                float4 bv1 = *(const float4*)&Bs[kk][tx * 8 + 4];
                float a[4] = {av.x, av.y, av.z, av.w};
                float b[8] = {bv0.x, bv0.y, bv0.z, bv0.w, bv1.x, bv1.y, bv1.z, bv1.w};
                #pragma unroll
                for (int r = 0; r < 4; r++)
                    #pragma unroll
                    for (int u = 0; u < 8; u++)
                        acc[r][u] += a[r] * b[u];
            }
        }
        __syncthreads();

        // epilogue: RBF + alpha reduction
        #pragma unroll
        for (int r = 0; r < 4; r++) {
            float fr2 = f2s[ty * 4 + r];
            #pragma unroll
            for (int u = 0; u < 8; u++) {
                int j = tx * 8 + u;
                float d2 = fr2 + s2s[j] - 2.0f * acc[r][u];
                float kv = __expf(-GAMMA * d2);
                float4 al = alpha_s[j];
                pout[r][0] += kv * al.x;
                pout[r][1] += kv * al.y;
                pout[r][2] += kv * al.z;
                pout[r][3] += kv * al.w;
            }
        }
        __syncthreads();  // protect alpha_s/s2s before next tile's loads
    }

    // reduce pout across the 16 tx lanes (stays within half-warp: ty fixed)
    #pragma unroll
    for (int off = 8; off; off >>= 1)
        #pragma unroll
        for (int r = 0; r < 4; r++)
            #pragma unroll
            for (int c = 0; c < 4; c++)
                pout[r][c] += __shfl_xor_sync(0xffffffffu, pout[r][c], off);

    if (tx == 0) {
        #pragma unroll
        for (int r = 0; r < 4; r++)
            #pragma unroll
            for (int c = 0; c < 4; c++)
                g_scratch[(size_t)(msplit * NIMG + ibase + ty * 4 + r) * NCLS + c] = pout[r][c];
    }
}

__global__ void combine_kernel(float* __restrict__ out)
{
    int i = blockIdx.x * blockDim.x + threadIdx.x;
    if (i < NIMG * NCLS) out[i] = g_scratch[i] + g_scratch[NIMG * NCLS + i];
}

// ---------------------------------------------------------------------------
extern "C" void kernel_launch(void* const* d_in, const int* in_sizes, int n_in,
                              void* d_out, int out_size)
{
    const float* x       = (const float*)d_in[0];
    const float* w1      = (const float*)d_in[1];
    const float* b1      = (const float*)d_in[2];
    const float* w2      = (const float*)d_in[3];
    const float* b2      = (const float*)d_in[4];
    const float* support = (const float*)d_in[5];
    const float* alpha   = (const float*)d_in[6];
    float* out = (float*)d_out;

    conv_kernel<<<NIMG, 128>>>(x, w1, b1, w2, b2);
    sumsq_kernel<<<(MSUP + NIMG) / 8, 256>>>(support);
    gemm_kernel<<<dim3(NIMG / BN, 2), 256>>>(support, alpha);
    combine_kernel<<<(NIMG * NCLS + 255) / 256, 256>>>(out);
}

// round 4
// speedup vs baseline: 6.9392x; 6.9392x over previous
#include <cuda_runtime.h>
#include <cuda_bf16.h>
#include <cstdint>

#define GAMMA 0.001f
#define NIMG 4096
#define MSUP 8192
#define KDIM 784
#define KPAD 800
#define NCLS 4

#define TI 128
#define TJ 128
#define KC 32
#define STA 40                 // padded smem row stride (elems): 80B, conflict-free
#define NSTAGE (KPAD / KC)     // 25
#define NJT (MSUP / TJ)        // 64
#define NIT (NIMG / TI)        // 32

// ---- device scratch (no allocs allowed) ----
__device__ __nv_bfloat16 g_featsB[NIMG * KPAD];
__device__ __nv_bfloat16 g_supB[MSUP * KPAD];
__device__ float g_s2[MSUP];
__device__ float g_f2[NIMG];
__device__ float g_part[NJT * NIMG * NCLS];

// ---------------------------------------------------------------------------
__device__ __forceinline__ uint32_t smem_u32(const void* p) {
    uint32_t a;
    asm("{ .reg .u64 t; cvta.to.shared.u64 t, %1; cvt.u32.u64 %0, t; }" : "=r"(a) : "l"(p));
    return a;
}
__device__ __forceinline__ void cp16(uint32_t smem, const void* gmem) {
    asm volatile("cp.async.cg.shared.global [%0], [%1], 16;" :: "r"(smem), "l"(gmem));
}
__device__ __forceinline__ void ldm_x4(uint32_t* r, uint32_t addr) {
    asm volatile("ldmatrix.sync.aligned.m8n8.x4.shared.b16 {%0,%1,%2,%3}, [%4];"
                 : "=r"(r[0]), "=r"(r[1]), "=r"(r[2]), "=r"(r[3]) : "r"(addr));
}
__device__ __forceinline__ void mma_bf16(float* d, const uint32_t* a, uint32_t b0, uint32_t b1) {
    asm volatile(
        "mma.sync.aligned.m16n8k16.row.col.f32.bf16.bf16.f32 "
        "{%0,%1,%2,%3}, {%4,%5,%6,%7}, {%8,%9}, {%0,%1,%2,%3};"
        : "+f"(d[0]), "+f"(d[1]), "+f"(d[2]), "+f"(d[3])
        : "r"(a[0]), "r"(a[1]), "r"(a[2]), "r"(a[3]), "r"(b0), "r"(b1));
}

// ---------------------------------------------------------------------------
// Conv pipeline: per-image block; writes bf16-rounded feats (padded to KPAD).
// ---------------------------------------------------------------------------
__global__ void __launch_bounds__(128) conv_kernel(
    const float* __restrict__ x,
    const float* __restrict__ w1, const float* __restrict__ b1,
    const float* __restrict__ w2, const float* __restrict__ b2)
{
    __shared__ float sx[30 * 30];
    __shared__ float sp1[8 * 16 * 16];
    __shared__ float sw1[72], sb1[8], sw2[1152], sb2[16];

    const int tid = threadIdx.x;
    const int n = blockIdx.x;

    for (int i = tid; i < 900; i += 128) sx[i] = 0.f;
    for (int i = tid; i < 2048; i += 128) sp1[i] = 0.f;
    for (int i = tid; i < 72; i += 128) sw1[i] = w1[i];
    if (tid < 8) sb1[tid] = b1[tid];
    for (int i = tid; i < 1152; i += 128) sw2[i] = w2[i];
    if (tid < 16) sb2[tid] = b2[tid];
    __syncthreads();

    const float* xn = x + (size_t)n * 784;
    for (int i = tid; i < 784; i += 128) {
        int yy = i / 28, xx = i % 28;
        sx[(yy + 1) * 30 + xx + 1] = xn[i];
    }
    __syncthreads();

    for (int o = tid; o < 8 * 14 * 14; o += 128) {
        int c = o / 196, rem = o % 196;
        int py = rem / 14, px = rem % 14;
        float m = 0.f;
        #pragma unroll
        for (int sy = 0; sy < 2; sy++)
            #pragma unroll
            for (int sxx = 0; sxx < 2; sxx++) {
                int y = py * 2 + sy, xx2 = px * 2 + sxx;
                float acc = sb1[c];
                #pragma unroll
                for (int dy = 0; dy < 3; dy++)
                    #pragma unroll
                    for (int dx = 0; dx < 3; dx++)
                        acc += sw1[c * 9 + dy * 3 + dx] * sx[(y + dy) * 30 + xx2 + dx];
                m = fmaxf(m, fmaxf(acc, 0.f));
            }
        sp1[c * 256 + (py + 1) * 16 + px + 1] = m;
    }
    __syncthreads();

    for (int o = tid; o < 16 * 7 * 7; o += 128) {
        int c = o / 49, rem = o % 49;
        int py = rem / 7, px = rem % 7;
        float m = 0.f;
        #pragma unroll
        for (int sy = 0; sy < 2; sy++)
            #pragma unroll
            for (int sxx = 0; sxx < 2; sxx++) {
                int y = py * 2 + sy, xx2 = px * 2 + sxx;
                float acc = sb2[c];
                #pragma unroll
                for (int ic = 0; ic < 8; ic++)
                    #pragma unroll
                    for (int dy = 0; dy < 3; dy++)
                        #pragma unroll
                        for (int dx = 0; dx < 3; dx++)
                            acc += sw2[c * 72 + ic * 9 + dy * 3 + dx] *
                                   sp1[ic * 256 + (y + dy) * 16 + xx2 + dx];
                m = fmaxf(m, fmaxf(acc, 0.f));
            }
        g_featsB[(size_t)n * KPAD + o] = __float2bfloat16(m);
    }
    if (tid < KPAD - KDIM) g_featsB[(size_t)n * KPAD + KDIM + tid] = __float2bfloat16(0.f);
}

// ---------------------------------------------------------------------------
// support -> g_supB (bf16) + g_s2 (fp32 from rounded). One warp per row.
// ---------------------------------------------------------------------------
__global__ void __launch_bounds__(256) prep_support(const float* __restrict__ support)
{
    int row = blockIdx.x * 8 + (threadIdx.x >> 5);
    int lane = threadIdx.x & 31;
    if (row >= MSUP) return;
    const float* src = support + (size_t)row * KDIM;
    __nv_bfloat16* dst = g_supB + (size_t)row * KPAD;
    float s = 0.f;
    for (int k = lane; k < KDIM; k += 32) {
        __nv_bfloat16 b = __float2bfloat16(src[k]);
        dst[k] = b;
        float v = __bfloat162float(b);
        s += v * v;
    }
    if (lane < KPAD - KDIM) dst[KDIM + lane] = __float2bfloat16(0.f);
    #pragma unroll
    for (int off = 16; off; off >>= 1) s += __shfl_xor_sync(0xffffffffu, s, off);
    if (lane == 0) g_s2[row] = s;
}

__global__ void __launch_bounds__(256) f2_kernel()
{
    int row = blockIdx.x * 8 + (threadIdx.x >> 5);
    int lane = threadIdx.x & 31;
    if (row >= NIMG) return;
    const __nv_bfloat16* src = g_featsB + (size_t)row * KPAD;
    float s = 0.f;
    for (int k = lane; k < KDIM; k += 32) {
        float v = __bfloat162float(src[k]);
        s += v * v;
    }
    #pragma unroll
    for (int off = 16; off; off >>= 1) s += __shfl_xor_sync(0xffffffffu, s, off);
    if (lane == 0) g_f2[row] = s;
}

// ---------------------------------------------------------------------------
// bf16 mma.sync fused GEMM: D = feats @ support^T (128x128 CTA tile),
// epilogue K = exp(-g*(f2+s2-2D)), partial[i][cls] += K*alpha per j-tile.
// ---------------------------------------------------------------------------
__global__ void __launch_bounds__(256, 2) gemm_mma(const float* __restrict__ alpha)
{
    __shared__ __nv_bfloat16 As[2][TI * STA];
    __shared__ __nv_bfloat16 Bs[2][TJ * STA];
    __shared__ float s2s[TJ], f2s[TI];
    __shared__ float4 als[TJ];
    float* red = (float*)As;   // [4 wj][128 rows][4 cls], reused after mainloop

    const int tid = threadIdx.x;
    const int lane = tid & 31, wid = tid >> 5;
    const int wi = wid >> 2;        // 0..1 : 64-row slice
    const int wj = wid & 3;         // 0..3 : 32-col slice
    const int ibase = blockIdx.x * TI;
    const int jbase = blockIdx.y * TJ;

    // prologue: f2/s2/alpha tiles
    if (tid < TI) f2s[tid] = g_f2[ibase + tid];
    if (tid < TJ) {
        s2s[tid] = g_s2[jbase + tid];
        als[tid] = ((const float4*)alpha)[jbase + tid];
    }

    const uint32_t aBase[2] = { smem_u32(As[0]), smem_u32(As[1]) };
    const uint32_t bBase[2] = { smem_u32(Bs[0]), smem_u32(Bs[1]) };
    const __nv_bfloat16* gA = g_featsB + (size_t)ibase * KPAD;
    const __nv_bfloat16* gB = g_supB + (size_t)jbase * KPAD;

    float acc[4][4][4];
    #pragma unroll
    for (int mi = 0; mi < 4; mi++)
        #pragma unroll
        for (int nj = 0; nj < 4; nj++)
            #pragma unroll
            for (int e = 0; e < 4; e++) acc[mi][nj][e] = 0.f;

    // cp.async staging helper (inlined twice via lambda)
    auto prefetch = [&](int s, int b) {
        #pragma unroll
        for (int t = 0; t < 2; t++) {
            int id = tid + t * 256;
            int r = id >> 2, c = id & 3;
            cp16(aBase[b] + (r * STA + c * 8) * 2, gA + (size_t)r * KPAD + s * KC + c * 8);
        }
        #pragma unroll
        for (int t = 0; t < 2; t++) {
            int id = tid + t * 256;
            int r = id >> 2, c = id & 3;
            cp16(bBase[b] + (r * STA + c * 8) * 2, gB + (size_t)r * KPAD + s * KC + c * 8);
        }
        asm volatile("cp.async.commit_group;" ::: "memory");
    };

    prefetch(0, 0);

    // per-lane ldmatrix address components
    const int a_row = (lane & 15);
    const int a_koff = (lane >> 4) * 8;
    const int b_nrow = ((lane >> 4) & 1) * 8 + (lane & 7);
    const int b_koff = ((lane >> 3) & 1) * 8;

    for (int s = 0; s < NSTAGE; s++) {
        const int b = s & 1;
        if (s + 1 < NSTAGE) {
            prefetch(s + 1, b ^ 1);
            asm volatile("cp.async.wait_group 1;" ::: "memory");
        } else {
            asm volatile("cp.async.wait_group 0;" ::: "memory");
        }
        __syncthreads();

        #pragma unroll
        for (int ks = 0; ks < 2; ks++) {
            uint32_t afr[4][4];
            #pragma unroll
            for (int mi = 0; mi < 4; mi++) {
                uint32_t addr = aBase[b] +
                    ((wi * 64 + mi * 16 + a_row) * STA + ks * 16 + a_koff) * 2;
                ldm_x4(afr[mi], addr);
            }
            uint32_t bfr[2][4];
            #pragma unroll
            for (int njp = 0; njp < 2; njp++) {
                uint32_t addr = bBase[b] +
                    ((wj * 32 + njp * 16 + b_nrow) * STA + ks * 16 + b_koff) * 2;
                ldm_x4(bfr[njp], addr);
            }
            #pragma unroll
            for (int mi = 0; mi < 4; mi++)
                #pragma unroll
                for (int nj = 0; nj < 4; nj++)
                    mma_bf16(acc[mi][nj], afr[mi],
                             bfr[nj >> 1][(nj & 1) * 2 + 0],
                             bfr[nj >> 1][(nj & 1) * 2 + 1]);
        }
        __syncthreads();
    }

    // ---------------- epilogue: RBF + alpha, fused ----------------
    const int r0 = lane >> 2;          // row-in-16 group
    const int c0 = (lane & 3) * 2;     // col pair base
    float po[8][4];
    #pragma unroll
    for (int i = 0; i < 8; i++)
        #pragma unroll
        for (int c = 0; c < 4; c++) po[i][c] = 0.f;

    #pragma unroll
    for (int mi = 0; mi < 4; mi++)
        #pragma unroll
        for (int nj = 0; nj < 4; nj++)
            #pragma unroll
            for (int e = 0; e < 4; e++) {
                int h = e >> 1;                           // row half (+8)
                int rowl = wi * 64 + mi * 16 + r0 + h * 8;
                int coll = wj * 32 + nj * 8 + c0 + (e & 1);
                float d2 = f2s[rowl] + s2s[coll] - 2.0f * acc[mi][nj][e];
                float kv = __expf(-GAMMA * d2);
                float4 al = als[coll];
                po[mi * 2 + h][0] += kv * al.x;
                po[mi * 2 + h][1] += kv * al.y;
                po[mi * 2 + h][2] += kv * al.z;
                po[mi * 2 + h][3] += kv * al.w;
            }

    // reduce over the 4 lanes sharing a row (lane&3 varies => different cols)
    #pragma unroll
    for (int off = 1; off <= 2; off <<= 1)
        #pragma unroll
        for (int i = 0; i < 8; i++)
            #pragma unroll
            for (int c = 0; c < 4; c++)
                po[i][c] += __shfl_xor_sync(0xffffffffu, po[i][c], off);

    if ((lane & 3) == 0) {
        #pragma unroll
        for (int i = 0; i < 8; i++) {
            int mi = i >> 1, h = i & 1;
            int rowl = wi * 64 + mi * 16 + r0 + h * 8;
            #pragma unroll
            for (int c = 0; c < 4; c++)
                red[(wj * TI + rowl) * 4 + c] = po[i][c];
        }
    }
    __syncthreads();

    for (int id = tid; id < TI * NCLS; id += 256) {
        int rowl = id >> 2, c = id & 3;
        float sum = red[(0 * TI + rowl) * 4 + c] + red[(1 * TI + rowl) * 4 + c]
                  + red[(2 * TI + rowl) * 4 + c] + red[(3 * TI + rowl) * 4 + c];
        g_part[(size_t)blockIdx.y * NIMG * NCLS + (size_t)(ibase + rowl) * NCLS + c] = sum;
    }
}

__global__ void combine_kernel(float* __restrict__ out)
{
    int i = blockIdx.x * blockDim.x + threadIdx.x;
    if (i >= NIMG * NCLS) return;
    float s = 0.f;
    #pragma unroll 8
    for (int p = 0; p < NJT; p++) s += g_part[(size_t)p * NIMG * NCLS + i];
    out[i] = s;
}

// ---------------------------------------------------------------------------
extern "C" void kernel_launch(void* const* d_in, const int* in_sizes, int n_in,
                              void* d_out, int out_size)
{
    const float* x       = (const float*)d_in[0];
    const float* w1      = (const float*)d_in[1];
    const float* b1      = (const float*)d_in[2];
    const float* w2      = (const float*)d_in[3];
    const float* b2      = (const float*)d_in[4];
    const float* support = (const float*)d_in[5];
    const float* alpha   = (const float*)d_in[6];
    float* out = (float*)d_out;

    conv_kernel<<<NIMG, 128>>>(x, w1, b1, w2, b2);
    f2_kernel<<<NIMG / 8, 256>>>();
    prep_support<<<MSUP / 8, 256>>>(support);
    gemm_mma<<<dim3(NIT, NJT), 256>>>(alpha);
    combine_kernel<<<(NIMG * NCLS + 255) / 256, 256>>>(out);
}

// round 5
// speedup vs baseline: 9.5204x; 1.3720x over previous
#include <cuda_runtime.h>
#include <cuda_bf16.h>
#include <cstdint>

#define GAMMA 0.001f
#define NIMG 4096
#define MSUP 8192
#define KDIM 784
#define KPAD 800
#define NCLS 4

#define TI 128
#define TJ 128
#define KC 32
#define STA 40                 // padded smem row stride (elems): 80B, conflict-free
#define NSTAGE (KPAD / KC)     // 25
#define NJT (MSUP / TJ)        // 64
#define NIT (NIMG / TI)        // 32

// ---- gemm dynamic smem layout (bytes) ----
#define OFF_A 0                          // 3 x TI*STA bf16 = 30720
#define OFF_B 30720                      // 3 x TJ*STA bf16 = 30720
#define OFF_S2 61440                     // 512
#define OFF_F2 61952                     // 512
#define OFF_AL 62464                     // 2048
#define GEMM_SMEM 64512

// ---- device scratch (no allocs allowed) ----
__device__ __nv_bfloat16 g_featsB[NIMG * KPAD];
__device__ __nv_bfloat16 g_supB[MSUP * KPAD];
__device__ float g_s2[MSUP];
__device__ float g_f2[NIMG];
__device__ float g_part[NJT * NIMG * NCLS];

// ---------------------------------------------------------------------------
__device__ __forceinline__ uint32_t smem_u32(const void* p) {
    uint32_t a;
    asm("{ .reg .u64 t; cvta.to.shared.u64 t, %1; cvt.u32.u64 %0, t; }" : "=r"(a) : "l"(p));
    return a;
}
__device__ __forceinline__ void cp16(uint32_t smem, const void* gmem) {
    asm volatile("cp.async.cg.shared.global [%0], [%1], 16;" :: "r"(smem), "l"(gmem));
}
__device__ __forceinline__ void ldm_x4(uint32_t* r, uint32_t addr) {
    asm volatile("ldmatrix.sync.aligned.m8n8.x4.shared.b16 {%0,%1,%2,%3}, [%4];"
                 : "=r"(r[0]), "=r"(r[1]), "=r"(r[2]), "=r"(r[3]) : "r"(addr));
}
__device__ __forceinline__ void mma_bf16(float* d, const uint32_t* a, uint32_t b0, uint32_t b1) {
    asm volatile(
        "mma.sync.aligned.m16n8k16.row.col.f32.bf16.bf16.f32 "
        "{%0,%1,%2,%3}, {%4,%5,%6,%7}, {%8,%9}, {%0,%1,%2,%3};"
        : "+f"(d[0]), "+f"(d[1]), "+f"(d[2]), "+f"(d[3])
        : "r"(a[0]), "r"(a[1]), "r"(a[2]), "r"(a[3]), "r"(b0), "r"(b1));
}

// ---------------------------------------------------------------------------
// Conv: 2 images per 256-thread block; register sliding-window, weights in
// regs; fuses bf16 feat store + f2 (sum of squares of rounded feats).
// ---------------------------------------------------------------------------
__global__ void __launch_bounds__(256) conv_kernel(
    const float* __restrict__ x,
    const float* __restrict__ w1, const float* __restrict__ b1,
    const float* __restrict__ w2, const float* __restrict__ b2)
{
    __shared__ float sx[2][900];          // 30x30 padded (+1)
    __shared__ float sp1[2][2048];        // 8 x 16x16 padded (+1)
    __shared__ float sw1[72], sb1[8], sw2[1152], sb2[16];
    __shared__ float sred[2][4];

    const int tid = threadIdx.x;
    const int img = tid >> 7;
    const int t = tid & 127;
    const int n = blockIdx.x * 2 + img;

    for (int i = tid; i < 1800; i += 256) ((float*)sx)[i] = 0.f;
    for (int i = tid; i < 4096; i += 256) ((float*)sp1)[i] = 0.f;
    for (int i = tid; i < 72; i += 256) sw1[i] = w1[i];
    if (tid < 8) sb1[tid] = b1[tid];
    for (int i = tid; i < 1152; i += 256) sw2[i] = w2[i];
    if (tid < 16) sb2[tid] = b2[tid];
    __syncthreads();

    const float* xn = x + (size_t)n * 784;
    for (int i = t; i < 784; i += 128) {
        int yy = i / 28, xx = i % 28;
        sx[img][(yy + 1) * 30 + xx + 1] = xn[i];
    }
    __syncthreads();

    // ---- conv1 + relu + pool: thread = (c in 0..7, px in 0..13) ----
    if (t < 112) {
        const int c = t & 7, px = t >> 3;
        float w[9];
        #pragma unroll
        for (int k = 0; k < 9; k++) w[k] = sw1[c * 9 + k];
        const float bb = sb1[c];
        const float* sxi = sx[img];
        float W[4][4];
        #pragma unroll
        for (int py = 0; py < 14; py++) {
            if (py == 0) {
                #pragma unroll
                for (int r = 0; r < 4; r++)
                    #pragma unroll
                    for (int cc = 0; cc < 4; cc++)
                        W[r][cc] = sxi[r * 30 + 2 * px + cc];
            } else {
                #pragma unroll
                for (int cc = 0; cc < 4; cc++) { W[0][cc] = W[2][cc]; W[1][cc] = W[3][cc]; }
                #pragma unroll
                for (int r = 2; r < 4; r++)
                    #pragma unroll
                    for (int cc = 0; cc < 4; cc++)
                        W[r][cc] = sxi[(2 * py + r) * 30 + 2 * px + cc];
            }
            float m = 0.f;
            #pragma unroll
            for (int sy = 0; sy < 2; sy++)
                #pragma unroll
                for (int sxx = 0; sxx < 2; sxx++) {
                    float acc = bb;
                    #pragma unroll
                    for (int dy = 0; dy < 3; dy++)
                        #pragma unroll
                        for (int dx = 0; dx < 3; dx++)
                            acc += w[dy * 3 + dx] * W[sy + dy][sxx + dx];
                    m = fmaxf(m, fmaxf(acc, 0.f));
                }
            sp1[img][c * 256 + (py + 1) * 16 + px + 1] = m;
        }
    }
    __syncthreads();

    // ---- conv2 + relu + pool: thread = (c in 0..15, px in 0..6) ----
    float sq = 0.f;
    if (t < 112) {
        const int px = t % 7, c = t / 7;
        float acc[7][4];
        const float bb = sb2[c];
        #pragma unroll
        for (int py = 0; py < 7; py++)
            #pragma unroll
            for (int q = 0; q < 4; q++) acc[py][q] = bb;

        #pragma unroll
        for (int ic = 0; ic < 8; ic++) {
            float w[9];
            #pragma unroll
            for (int k = 0; k < 9; k++) w[k] = sw2[c * 72 + ic * 9 + k];
            const float* sp = sp1[img] + ic * 256;
            float W[4][4];
            #pragma unroll
            for (int py = 0; py < 7; py++) {
                if (py == 0) {
                    #pragma unroll
                    for (int r = 0; r < 4; r++)
                        #pragma unroll
                        for (int cc = 0; cc < 4; cc++)
                            W[r][cc] = sp[r * 16 + 2 * px + cc];
                } else {
                    #pragma unroll
                    for (int cc = 0; cc < 4; cc++) { W[0][cc] = W[2][cc]; W[1][cc] = W[3][cc]; }
                    #pragma unroll
                    for (int r = 2; r < 4; r++)
                        #pragma unroll
                        for (int cc = 0; cc < 4; cc++)
                            W[r][cc] = sp[(2 * py + r) * 16 + 2 * px + cc];
                }
                #pragma unroll
                for (int sy = 0; sy < 2; sy++)
                    #pragma unroll
                    for (int sxx = 0; sxx < 2; sxx++) {
                        float a2 = 0.f;
                        #pragma unroll
                        for (int dy = 0; dy < 3; dy++)
                            #pragma unroll
                            for (int dx = 0; dx < 3; dx++)
                                a2 += w[dy * 3 + dx] * W[sy + dy][sxx + dx];
                        acc[py][sy * 2 + sxx] += a2;
                    }
            }
        }
        __nv_bfloat16* fdst = g_featsB + (size_t)n * KPAD + c * 49 + px;
        #pragma unroll
        for (int py = 0; py < 7; py++) {
            float m = 0.f;
            #pragma unroll
            for (int q = 0; q < 4; q++) m = fmaxf(m, fmaxf(acc[py][q], 0.f));
            __nv_bfloat16 bv = __float2bfloat16(m);
            fdst[py * 7] = bv;
            float fv = __bfloat162float(bv);
            sq += fv * fv;
        }
    }
    if (t < KPAD - KDIM)
        g_featsB[(size_t)n * KPAD + KDIM + t] = __float2bfloat16(0.f);

    // f2 block reduction (per image: 4 warps)
    #pragma unroll
    for (int off = 16; off; off >>= 1) sq += __shfl_xor_sync(0xffffffffu, sq, off);
    if ((t & 31) == 0) sred[img][(t >> 5) & 3] = sq;
    __syncthreads();
    if (t == 0) g_f2[n] = sred[img][0] + sred[img][1] + sred[img][2] + sred[img][3];
}

// ---------------------------------------------------------------------------
// support -> g_supB (bf16) + g_s2 (fp32 from rounded). One warp per row.
// ---------------------------------------------------------------------------
__global__ void __launch_bounds__(256) prep_support(const float* __restrict__ support)
{
    int row = blockIdx.x * 8 + (threadIdx.x >> 5);
    int lane = threadIdx.x & 31;
    if (row >= MSUP) return;
    const float* src = support + (size_t)row * KDIM;
    __nv_bfloat16* dst = g_supB + (size_t)row * KPAD;
    float s = 0.f;
    for (int k = lane; k < KDIM; k += 32) {
        __nv_bfloat16 b = __float2bfloat16(src[k]);
        dst[k] = b;
        float v = __bfloat162float(b);
        s += v * v;
    }
    if (lane < KPAD - KDIM) dst[KDIM + lane] = __float2bfloat16(0.f);
    #pragma unroll
    for (int off = 16; off; off >>= 1) s += __shfl_xor_sync(0xffffffffu, s, off);
    if (lane == 0) g_s2[row] = s;
}

// ---------------------------------------------------------------------------
// bf16 mma.sync fused GEMM, 3-stage cp.async pipeline (dynamic smem).
// ---------------------------------------------------------------------------
__global__ void __launch_bounds__(256, 2) gemm_mma(const float* __restrict__ alpha)
{
    extern __shared__ char dsm[];
    float* s2s = (float*)(dsm + OFF_S2);
    float* f2s = (float*)(dsm + OFF_F2);
    float4* als = (float4*)(dsm + OFF_AL);
    float* red = (float*)(dsm + OFF_A);   // reused after mainloop

    const int tid = threadIdx.x;
    const int lane = tid & 31, wid = tid >> 5;
    const int wi = wid >> 2;        // 0..1 : 64-row slice
    const int wj = wid & 3;         // 0..3 : 32-col slice
    const int ibase = blockIdx.x * TI;
    const int jbase = blockIdx.y * TJ;

    if (tid < TI) f2s[tid] = g_f2[ibase + tid];
    if (tid < TJ) {
        s2s[tid] = g_s2[jbase + tid];
        als[tid] = ((const float4*)alpha)[jbase + tid];
    }

    uint32_t aBase[3], bBase[3];
    #pragma unroll
    for (int b = 0; b < 3; b++) {
        aBase[b] = smem_u32(dsm + OFF_A + b * TI * STA * 2);
        bBase[b] = smem_u32(dsm + OFF_B + b * TJ * STA * 2);
    }
    const __nv_bfloat16* gA = g_featsB + (size_t)ibase * KPAD;
    const __nv_bfloat16* gB = g_supB + (size_t)jbase * KPAD;

    float acc[4][4][4];
    #pragma unroll
    for (int mi = 0; mi < 4; mi++)
        #pragma unroll
        for (int nj = 0; nj < 4; nj++)
            #pragma unroll
            for (int e = 0; e < 4; e++) acc[mi][nj][e] = 0.f;

    auto prefetch = [&](int s, int b) {
        #pragma unroll
        for (int tcnt = 0; tcnt < 2; tcnt++) {
            int id = tid + tcnt * 256;
            int r = id >> 2, c = id & 3;
            cp16(aBase[b] + (r * STA + c * 8) * 2, gA + (size_t)r * KPAD + s * KC + c * 8);
        }
        #pragma unroll
        for (int tcnt = 0; tcnt < 2; tcnt++) {
            int id = tid + tcnt * 256;
            int r = id >> 2, c = id & 3;
            cp16(bBase[b] + (r * STA + c * 8) * 2, gB + (size_t)r * KPAD + s * KC + c * 8);
        }
        asm volatile("cp.async.commit_group;" ::: "memory");
    };

    prefetch(0, 0);
    prefetch(1, 1);

    const int a_row = (lane & 15);
    const int a_koff = (lane >> 4) * 8;
    const int b_nrow = ((lane >> 4) & 1) * 8 + (lane & 7);
    const int b_koff = ((lane >> 3) & 1) * 8;

    for (int s = 0; s < NSTAGE; s++) {
        if (s + 2 < NSTAGE) {
            prefetch(s + 2, (s + 2) % 3);
            asm volatile("cp.async.wait_group 2;" ::: "memory");
        } else if (s + 1 < NSTAGE) {
            asm volatile("cp.async.wait_group 1;" ::: "memory");
        } else {
            asm volatile("cp.async.wait_group 0;" ::: "memory");
        }
        __syncthreads();

        const int b = s % 3;
        #pragma unroll
        for (int ks = 0; ks < 2; ks++) {
            uint32_t afr[4][4];
            #pragma unroll
            for (int mi = 0; mi < 4; mi++) {
                uint32_t addr = aBase[b] +
                    ((wi * 64 + mi * 16 + a_row) * STA + ks * 16 + a_koff) * 2;
                ldm_x4(afr[mi], addr);
            }
            uint32_t bfr[2][4];
            #pragma unroll
            for (int njp = 0; njp < 2; njp++) {
                uint32_t addr = bBase[b] +
                    ((wj * 32 + njp * 16 + b_nrow) * STA + ks * 16 + b_koff) * 2;
                ldm_x4(bfr[njp], addr);
            }
            #pragma unroll
            for (int mi = 0; mi < 4; mi++)
                #pragma unroll
                for (int nj = 0; nj < 4; nj++)
                    mma_bf16(acc[mi][nj], afr[mi],
                             bfr[nj >> 1][(nj & 1) * 2 + 0],
                             bfr[nj >> 1][(nj & 1) * 2 + 1]);
        }
        __syncthreads();
    }

    // ---------------- epilogue: RBF + alpha, fused ----------------
    const int r0 = lane >> 2;
    const int c0 = (lane & 3) * 2;
    float po[8][4];
    #pragma unroll
    for (int i = 0; i < 8; i++)
        #pragma unroll
        for (int c = 0; c < 4; c++) po[i][c] = 0.f;

    #pragma unroll
    for (int mi = 0; mi < 4; mi++)
        #pragma unroll
        for (int nj = 0; nj < 4; nj++)
            #pragma unroll
            for (int e = 0; e < 4; e++) {
                int h = e >> 1;
                int rowl = wi * 64 + mi * 16 + r0 + h * 8;
                int coll = wj * 32 + nj * 8 + c0 + (e & 1);
                float d2 = f2s[rowl] + s2s[coll] - 2.0f * acc[mi][nj][e];
                float kv = __expf(-GAMMA * d2);
                float4 al = als[coll];
                po[mi * 2 + h][0] += kv * al.x;
                po[mi * 2 + h][1] += kv * al.y;
                po[mi * 2 + h][2] += kv * al.z;
                po[mi * 2 + h][3] += kv * al.w;
            }

    #pragma unroll
    for (int off = 1; off <= 2; off <<= 1)
        #pragma unroll
        for (int i = 0; i < 8; i++)
            #pragma unroll
            for (int c = 0; c < 4; c++)
                po[i][c] += __shfl_xor_sync(0xffffffffu, po[i][c], off);

    if ((lane & 3) == 0) {
        #pragma unroll
        for (int i = 0; i < 8; i++) {
            int mi = i >> 1, h = i & 1;
            int rowl = wi * 64 + mi * 16 + r0 + h * 8;
            #pragma unroll
            for (int c = 0; c < 4; c++)
                red[(wj * TI + rowl) * 4 + c] = po[i][c];
        }
    }
    __syncthreads();

    for (int id = tid; id < TI * NCLS; id += 256) {
        int rowl = id >> 2, c = id & 3;
        float sum = red[(0 * TI + rowl) * 4 + c] + red[(1 * TI + rowl) * 4 + c]
                  + red[(2 * TI + rowl) * 4 + c] + red[(3 * TI + rowl) * 4 + c];
        g_part[(size_t)blockIdx.y * NIMG * NCLS + (size_t)(ibase + rowl) * NCLS + c] = sum;
    }
}

__global__ void combine_kernel(float* __restrict__ out)
{
    int i = blockIdx.x * blockDim.x + threadIdx.x;
    if (i >= NIMG * NCLS) return;
    float s = 0.f;
    #pragma unroll 8
    for (int p = 0; p < NJT; p++) s += g_part[(size_t)p * NIMG * NCLS + i];
    out[i] = s;
}

// ---------------------------------------------------------------------------
extern "C" void kernel_launch(void* const* d_in, const int* in_sizes, int n_in,
                              void* d_out, int out_size)
{
    const float* x       = (const float*)d_in[0];
    const float* w1      = (const float*)d_in[1];
    const float* b1      = (const float*)d_in[2];
    const float* w2      = (const float*)d_in[3];
    const float* b2      = (const float*)d_in[4];
    const float* support = (const float*)d_in[5];
    const float* alpha   = (const float*)d_in[6];
    float* out = (float*)d_out;

    static bool attr_set = false;
    if (!attr_set) {
        cudaFuncSetAttribute(gemm_mma, cudaFuncAttributeMaxDynamicSharedMemorySize, GEMM_SMEM);
        attr_set = true;
    }

    conv_kernel<<<NIMG / 2, 256>>>(x, w1, b1, w2, b2);
    prep_support<<<MSUP / 8, 256>>>(support);
    gemm_mma<<<dim3(NIT, NJT), 256, GEMM_SMEM>>>(alpha);
    combine_kernel<<<(NIMG * NCLS + 255) / 256, 256>>>(out);
}